// round 1
// baseline (speedup 1.0000x reference)
#include <cuda_runtime.h>
#include <math.h>

#define BATCH 4
#define SEQ   4096
#define HDIM  64
#define BQ    64     // queries per block (= threads per block)
#define BK    32     // keys per shared tile
#define NTILES (SEQ / BK)

// One thread owns one query row. Online softmax over the FULL row (stats over
// all keys), V accumulation gated to k <= q (post-softmax causal zeroing).
__global__ __launch_bounds__(BQ, 4)
void attn_fullsoftmax_causal_kernel(const float* __restrict__ qg,
                                    const float* __restrict__ kg,
                                    const float* __restrict__ vg,
                                    float* __restrict__ outg) {
    __shared__ float Ksh[BK][HDIM];
    __shared__ float Vsh[BK][HDIM];

    const int b  = blockIdx.y;
    const int t  = threadIdx.x;
    const int qi = blockIdx.x * BQ + t;        // global query index in sequence

    // ---- load this thread's query row into registers, pre-scaled by 1/sqrt(D)
    const float4* qrow = (const float4*)(qg + ((size_t)b * SEQ + qi) * HDIM);
    float4 qr[HDIM / 4];
    #pragma unroll
    for (int i = 0; i < HDIM / 4; i++) {
        float4 x = qrow[i];
        x.x *= 0.125f; x.y *= 0.125f; x.z *= 0.125f; x.w *= 0.125f;
        qr[i] = x;
    }

    float acc[HDIM];
    #pragma unroll
    for (int d = 0; d < HDIM; d++) acc[d] = 0.0f;
    float m = -INFINITY;
    float l = 0.0f;

    const float* kb = kg + (size_t)b * SEQ * HDIM;
    const float* vb = vg + (size_t)b * SEQ * HDIM;

    for (int kt = 0; kt < NTILES; kt++) {
        // ---- cooperative tile load: BK*HDIM floats = 512 float4, 64 threads -> 8 each
        {
            const float4* ks = (const float4*)(kb + (size_t)kt * BK * HDIM);
            const float4* vs = (const float4*)(vb + (size_t)kt * BK * HDIM);
            float4* Kd = (float4*)&Ksh[0][0];
            float4* Vd = (float4*)&Vsh[0][0];
            #pragma unroll
            for (int i = 0; i < (BK * HDIM / 4) / BQ; i++) {
                Kd[t + i * BQ] = ks[t + i * BQ];
                Vd[t + i * BQ] = vs[t + i * BQ];
            }
        }
        __syncthreads();

        // ---- scores for this tile (broadcast LDS.128, 4 partial sums for ILP)
        float sreg[BK];
        float tmax = -INFINITY;
        #pragma unroll
        for (int j = 0; j < BK; j++) {
            const float4* kr = (const float4*)Ksh[j];
            float s0 = 0.f, s1 = 0.f, s2 = 0.f, s3 = 0.f;
            #pragma unroll
            for (int i = 0; i < HDIM / 4; i++) {
                float4 kv = kr[i];
                s0 = fmaf(qr[i].x, kv.x, s0);
                s1 = fmaf(qr[i].y, kv.y, s1);
                s2 = fmaf(qr[i].z, kv.z, s2);
                s3 = fmaf(qr[i].w, kv.w, s3);
            }
            float sj = (s0 + s1) + (s2 + s3);
            sreg[j] = sj;
            tmax = fmaxf(tmax, sj);
        }

        // ---- online softmax update (stats over ALL keys)
        const float m_new = fmaxf(m, tmax);
        const float corr  = __expf(m - m_new);   // 0 on first tile (m = -inf)
        l *= corr;
        #pragma unroll
        for (int d = 0; d < HDIM; d++) acc[d] *= corr;
        #pragma unroll
        for (int j = 0; j < BK; j++) {
            float p = __expf(sreg[j] - m_new);
            l += p;
            sreg[j] = p;
        }
        m = m_new;

        // ---- causal-gated V accumulation: only keys with global index <= qi
        const int base = kt * BK;
        if (base <= qi) {
            const int jmax = min(BK, qi - base + 1);
            for (int j = 0; j < jmax; j++) {
                const float p = sreg[j];
                const float4* vr = (const float4*)Vsh[j];
                #pragma unroll
                for (int i = 0; i < HDIM / 4; i++) {
                    float4 vv = vr[i];
                    acc[4 * i + 0] = fmaf(p, vv.x, acc[4 * i + 0]);
                    acc[4 * i + 1] = fmaf(p, vv.y, acc[4 * i + 1]);
                    acc[4 * i + 2] = fmaf(p, vv.z, acc[4 * i + 2]);
                    acc[4 * i + 3] = fmaf(p, vv.w, acc[4 * i + 3]);
                }
            }
        }
        __syncthreads();
    }

    // ---- epilogue: divide by full-row partition function and store
    const float inv_l = 1.0f / l;
    float4* orow = (float4*)(outg + ((size_t)b * SEQ + qi) * HDIM);
    #pragma unroll
    for (int i = 0; i < HDIM / 4; i++) {
        float4 o;
        o.x = acc[4 * i + 0] * inv_l;
        o.y = acc[4 * i + 1] * inv_l;
        o.z = acc[4 * i + 2] * inv_l;
        o.w = acc[4 * i + 3] * inv_l;
        orow[i] = o;
    }
}

extern "C" void kernel_launch(void* const* d_in, const int* in_sizes, int n_in,
                              void* d_out, int out_size) {
    const float* q = (const float*)d_in[0];
    const float* k = (const float*)d_in[1];
    const float* v = (const float*)d_in[2];
    float* out = (float*)d_out;

    dim3 grid(SEQ / BQ, BATCH);
    dim3 block(BQ);
    attn_fullsoftmax_causal_kernel<<<grid, block>>>(q, k, v, out);
}